// round 4
// baseline (speedup 1.0000x reference)
#include <cuda_runtime.h>
#include <cuda_bf16.h>
#include <cstdint>

// ---------------------------------------------------------------------------
// Fused two-tower scorer, round 4:
//  - prep kernel pre-rounds (cvt.rna.tf32) + permutes uW/iW into __device__
//    scratch -> main loop has zero W cvts and cp.async's W directly.
//  - permuted smem layout (k=4j+t stored at t*8+j) -> all fragment loads are
//    aligned LDS.128 (8x fewer LDS issues than round 3).
//  - W triple-buffered cp.async, A LDG.128 -> cvt -> STS one chunk ahead.
// ---------------------------------------------------------------------------

#define NTHREADS 256
#define TB       128     // batch rows per CTA
#define LOUT     256     // latents (GEMM N)
#define KF       512     // features (GEMM K)
#define KC       32      // K chunk (floats)
#define NCHUNK   32      // 16 chunks/tower x 2 towers
#define AST      36      // A smem row stride (floats)
#define WST      36      // W smem row stride (floats)
#define ULST     264     // user-latent smem stride (bf16)

// smem byte offsets
#define S_IDXU   0
#define S_IDXI   512
#define S_UB     1024
#define S_IB     2048
#define S_PART   3072
#define S_ULAT   3584                    // 128 x 264 bf16 = 67584
#define S_A      71168                   // A tiles, double buffered
#define A_BYTES  (TB * AST * 4)          // 18432
#define S_W      (S_A + 2 * A_BYTES)     // 108032, W tiles triple buffered
#define W_BYTES  (LOUT * WST * 4)        // 36864
#define S_TOTAL  (S_W + 3 * W_BYTES)     // 218624

// pre-rounded, permuted weights: [tower][l][512] with per-chunk permutation
__device__ float wscr[2 * LOUT * KF];

// --------------------------- helpers ----------------------------------------

__device__ __forceinline__ float tf32f(float x) {
    uint32_t u;
    asm("cvt.rna.tf32.f32 %0, %1;" : "=r"(u) : "f"(x));
    return __uint_as_float(u);
}

__device__ __forceinline__ void mma8(float* c, uint32_t a0, uint32_t a1,
                                     uint32_t a2, uint32_t a3,
                                     uint32_t b0, uint32_t b1) {
    asm volatile(
        "mma.sync.aligned.m16n8k8.row.col.f32.tf32.tf32.f32 "
        "{%0,%1,%2,%3}, {%4,%5,%6,%7}, {%8,%9}, {%0,%1,%2,%3};"
        : "+f"(c[0]), "+f"(c[1]), "+f"(c[2]), "+f"(c[3])
        : "r"(a0), "r"(a1), "r"(a2), "r"(a3), "r"(b0), "r"(b1));
}

__device__ __forceinline__ void cp16(uint32_t dst, const float* src) {
    asm volatile("cp.async.cg.shared.global [%0], [%1], 16;"
                 :: "r"(dst), "l"(src) : "memory");
}

// W chunk c -> smem buffer c%3 (scratch is already rounded + permuted)
__device__ __forceinline__ void issue_w(int c, uint32_t sb, int tid) {
    const int tower = c >> 4, ch = c & 15, buf = c % 3;
    const float* src0 = wscr + tower * (LOUT * KF) + ch * KC;
    const uint32_t dst0 = sb + S_W + buf * W_BYTES;
#pragma unroll
    for (int i = 0; i < 8; i++) {            // 2048 16B segments
        int seg = tid + i * NTHREADS;
        int row = seg >> 3, sgq = seg & 7;
        cp16(dst0 + row * (WST * 4) + sgq * 16, src0 + row * KF + sgq * 4);
    }
    asm volatile("cp.async.commit_group;" ::: "memory");
}

__device__ __forceinline__ void ldg_a(float4* pref, const float* lut,
                                      const int* idx, int kc, int tid) {
#pragma unroll
    for (int i = 0; i < 4; i++) {            // 1024 16B segments
        int seg = tid + i * NTHREADS;
        int row = seg >> 3, q = seg & 7;
        pref[i] = __ldg(reinterpret_cast<const float4*>(
            lut + (size_t)idx[row] * KF + kc + q * 4));
    }
}

// store A chunk with rna rounding + permutation: k=4q+r -> pos r*8+q
__device__ __forceinline__ void sts_a(const float4* pref, char* smem, int c,
                                      int tid) {
    float* base = (float*)(smem + S_A + (c & 1) * A_BYTES);
#pragma unroll
    for (int i = 0; i < 4; i++) {
        int seg = tid + i * NTHREADS;
        int row = seg >> 3, q = seg & 7;
        float* rp = base + row * AST + q;
        rp[0]  = tf32f(pref[i].x);
        rp[8]  = tf32f(pref[i].y);
        rp[16] = tf32f(pref[i].z);
        rp[24] = tf32f(pref[i].w);
    }
}

// --------------------------- prep kernel ------------------------------------

__global__ void prep_kernel(const float* __restrict__ uW,
                            const float* __restrict__ iW) {
    int o = blockIdx.x * NTHREADS + threadIdx.x;   // [0, 262144)
    int tower = o >> 17;
    int l = (o >> 9) & (LOUT - 1);
    int p = o & (KF - 1);
    int ch = p >> 5, t = (p >> 3) & 3, j = p & 7;
    const float* W = tower ? iW : uW;
    wscr[o] = tf32f(W[l * KF + ch * KC + 4 * j + t]);
}

// --------------------------- main kernel ------------------------------------

__global__ void __launch_bounds__(NTHREADS, 1) towers_kernel(
    const int* __restrict__ x,
    const float* __restrict__ ulut, const float* __restrict__ ilut,
    const float* __restrict__ ubias, const float* __restrict__ ibias,
    float* __restrict__ out) {
    extern __shared__ char smem[];
    uint32_t sb;
    asm("{ .reg .u64 t; cvta.to.shared.u64 t, %1; cvt.u32.u64 %0, t; }"
        : "=r"(sb) : "l"(smem));
    const int tid  = threadIdx.x;
    const int lane = tid & 31;
    const int wid  = tid >> 5;
    const int wm   = wid & 1;        // 64 rows each
    const int wn   = wid >> 1;       // 64 latents each
    const int g    = lane >> 2;
    const int t    = lane & 3;

    int*   idxu = (int*)(smem + S_IDXU);
    int*   idxi = (int*)(smem + S_IDXI);
    float* ubS  = (float*)(smem + S_UB);
    float* ibS  = (float*)(smem + S_IB);
    float* part = (float*)(smem + S_PART);
    __nv_bfloat16* ulat = (__nv_bfloat16*)(smem + S_ULAT);

    ubS[tid] = ubias[tid];
    ibS[tid] = ibias[tid];
    if (tid < TB) {
        part[tid] = 0.f;
        int gg = blockIdx.x * TB + tid;
        idxu[tid] = x[2 * gg];
        idxi[tid] = x[2 * gg + 1];
    }
    __syncthreads();

    issue_w(0, sb, tid);
    issue_w(1, sb, tid);

    float4 pref[4];
    ldg_a(pref, ulut, idxu, 0, tid);

    float acc[4][8][4];
#pragma unroll
    for (int mt = 0; mt < 4; mt++)
#pragma unroll
        for (int nt = 0; nt < 8; nt++)
#pragma unroll
            for (int i = 0; i < 4; i++) acc[mt][nt][i] = 0.f;

    for (int c = 0; c < NCHUNK; c++) {
        // 1. store prefetched A (rounds + permutes); buffer (c&1) is free:
        //    its last reader MMA(c-2) is CTA-wide complete past sync(c-1).
        sts_a(pref, smem, c, tid);

        // 2. prefetch next A chunk
        if (c + 1 < NCHUNK) {
            int c2 = c + 1;
            bool t2 = (c2 >= NCHUNK / 2);
            ldg_a(pref, t2 ? ilut : ulut, t2 ? idxi : idxu,
                  (c2 & 15) * KC, tid);
        }

        // 3. ensure W chunk c landed (newest outstanding group is c+1)
        if (c <= NCHUNK - 3)
            asm volatile("cp.async.wait_group 1;" ::: "memory");
        else
            asm volatile("cp.async.wait_group 0;" ::: "memory");
        __syncthreads();

        // 4. refill W pipeline (post-sync: buffer (c+2)%3's readers are done)
        if (c + 2 < NCHUNK) issue_w(c + 2, sb, tid);

        // 5. MMA on chunk c
        const float* A  = (const float*)(smem + S_A + (c & 1) * A_BYTES);
        const float* Bs = (const float*)(smem + S_W + (c % 3) * W_BYTES);
#pragma unroll
        for (int h = 0; h < 2; h++) {        // two k-step pairs
            float4 alo[4], ahi[4];
#pragma unroll
            for (int mt = 0; mt < 4; mt++) {
                const int r0 = wm * 64 + mt * 16 + g;
                alo[mt] = *(const float4*)(A + r0 * AST + t * 8 + h * 4);
                ahi[mt] = *(const float4*)(A + (r0 + 8) * AST + t * 8 + h * 4);
            }
#pragma unroll
            for (int ntb = 0; ntb < 2; ntb++) {   // 4 nt at a time (regs)
                float4 bv[4];
#pragma unroll
                for (int n4 = 0; n4 < 4; n4++) {
                    const int n0 = wn * 64 + (ntb * 4 + n4) * 8 + g;
                    bv[n4] = *(const float4*)(Bs + n0 * WST + t * 8 + h * 4);
                }
#pragma unroll
                for (int sp = 0; sp < 2; sp++) {
#pragma unroll
                    for (int mt = 0; mt < 4; mt++) {
                        const float* al = (const float*)&alo[mt];
                        const float* ah = (const float*)&ahi[mt];
                        uint32_t a0 = __float_as_uint(al[2 * sp]);
                        uint32_t a1 = __float_as_uint(ah[2 * sp]);
                        uint32_t a2 = __float_as_uint(al[2 * sp + 1]);
                        uint32_t a3 = __float_as_uint(ah[2 * sp + 1]);
#pragma unroll
                        for (int n4 = 0; n4 < 4; n4++) {
                            const float* bp = (const float*)&bv[n4];
                            mma8(acc[mt][ntb * 4 + n4],
                                 a0, a1, a2, a3,
                                 __float_as_uint(bp[2 * sp]),
                                 __float_as_uint(bp[2 * sp + 1]));
                        }
                    }
                }
            }
        }

        // 6. user-tower epilogue: bias + relu -> bf16 smem, reset acc
        if (c == NCHUNK / 2 - 1) {
#pragma unroll
            for (int mt = 0; mt < 4; mt++) {
                const int r0 = wm * 64 + mt * 16 + g;
#pragma unroll
                for (int nt = 0; nt < 8; nt++) {
                    const int c0 = wn * 64 + nt * 8 + 2 * t;
                    float u0 = fmaxf(acc[mt][nt][0] + ubS[c0],     0.f);
                    float u1 = fmaxf(acc[mt][nt][1] + ubS[c0 + 1], 0.f);
                    float u2 = fmaxf(acc[mt][nt][2] + ubS[c0],     0.f);
                    float u3 = fmaxf(acc[mt][nt][3] + ubS[c0 + 1], 0.f);
                    *(__nv_bfloat162*)(ulat + r0 * ULST + c0) =
                        __floats2bfloat162_rn(u0, u1);
                    *(__nv_bfloat162*)(ulat + (r0 + 8) * ULST + c0) =
                        __floats2bfloat162_rn(u2, u3);
                    acc[mt][nt][0] = acc[mt][nt][1] = 0.f;
                    acc[mt][nt][2] = acc[mt][nt][3] = 0.f;
                }
            }
        }
    }

    // item-tower epilogue: bias+relu, product with user latent, row-reduce
#pragma unroll
    for (int mt = 0; mt < 4; mt++) {
        const int r0 = wm * 64 + mt * 16 + g;
        float s0 = 0.f, s1 = 0.f;
#pragma unroll
        for (int nt = 0; nt < 8; nt++) {
            const int c0 = wn * 64 + nt * 8 + 2 * t;
            float v0 = fmaxf(acc[mt][nt][0] + ibS[c0],     0.f);
            float v1 = fmaxf(acc[mt][nt][1] + ibS[c0 + 1], 0.f);
            float v2 = fmaxf(acc[mt][nt][2] + ibS[c0],     0.f);
            float v3 = fmaxf(acc[mt][nt][3] + ibS[c0 + 1], 0.f);
            float2 u01 = __bfloat1622float2(
                *(__nv_bfloat162*)(ulat + r0 * ULST + c0));
            float2 u23 = __bfloat1622float2(
                *(__nv_bfloat162*)(ulat + (r0 + 8) * ULST + c0));
            s0 = fmaf(u01.x, v0, fmaf(u01.y, v1, s0));
            s1 = fmaf(u23.x, v2, fmaf(u23.y, v3, s1));
        }
        s0 += __shfl_xor_sync(0xffffffffu, s0, 1);
        s0 += __shfl_xor_sync(0xffffffffu, s0, 2);
        s1 += __shfl_xor_sync(0xffffffffu, s1, 1);
        s1 += __shfl_xor_sync(0xffffffffu, s1, 2);
        if (t == 0) {
            atomicAdd(&part[r0], s0);
            atomicAdd(&part[r0 + 8], s1);
        }
    }
    __syncthreads();

    if (tid < TB) out[blockIdx.x * TB + tid] = part[tid];
}

// --------------------------- launch -----------------------------------------

extern "C" void kernel_launch(void* const* d_in, const int* in_sizes, int n_in,
                              void* d_out, int out_size) {
    const int* x      = (const int*)d_in[0];
    const float* ulut = (const float*)d_in[1];
    const float* ilut = (const float*)d_in[2];
    const float* uW   = (const float*)d_in[3];
    const float* ub   = (const float*)d_in[4];
    const float* iW   = (const float*)d_in[5];
    const float* ib   = (const float*)d_in[6];
    float* out        = (float*)d_out;

    prep_kernel<<<2 * LOUT * KF / NTHREADS, NTHREADS>>>(uW, iW);

    cudaFuncSetAttribute(towers_kernel,
                         cudaFuncAttributeMaxDynamicSharedMemorySize, S_TOTAL);
    int grid = out_size / TB;   // 128
    towers_kernel<<<grid, NTHREADS, S_TOTAL>>>(x, ulut, ilut, ub, ib, out);
}

// round 5
// speedup vs baseline: 1.4838x; 1.4838x over previous
#include <cuda_runtime.h>
#include <cuda_bf16.h>
#include <cstdint>

// ---------------------------------------------------------------------------
// Fused two-tower scorer, round 5: R4 pipeline at 512 threads (16 warps,
// 4 warps/SMSP) to hide LDS/MMA latency. Warp tile 32x64, acc 64 regs.
// ---------------------------------------------------------------------------

#define NTHREADS 512
#define TB       128     // batch rows per CTA
#define LOUT     256     // latents (GEMM N)
#define KF       512     // features (GEMM K)
#define KC       32      // K chunk (floats)
#define NCHUNK   32      // 16 chunks/tower x 2 towers
#define AST      36      // A smem row stride (floats)
#define WST      36      // W smem row stride (floats)
#define ULST     264     // user-latent smem stride (bf16)

// smem byte offsets
#define S_IDXU   0
#define S_IDXI   512
#define S_UB     1024
#define S_IB     2048
#define S_PART   3072
#define S_ULAT   3584                    // 128 x 264 bf16 = 67584
#define S_A      71168                   // A tiles, double buffered
#define A_BYTES  (TB * AST * 4)          // 18432
#define S_W      (S_A + 2 * A_BYTES)     // 108032, W tiles triple buffered
#define W_BYTES  (LOUT * WST * 4)        // 36864
#define S_TOTAL  (S_W + 3 * W_BYTES)     // 218624

// pre-rounded, permuted weights: [tower][l][512] with per-chunk permutation
__device__ float wscr[2 * LOUT * KF];

// --------------------------- helpers ----------------------------------------

__device__ __forceinline__ float tf32f(float x) {
    uint32_t u;
    asm("cvt.rna.tf32.f32 %0, %1;" : "=r"(u) : "f"(x));
    return __uint_as_float(u);
}

__device__ __forceinline__ void mma8(float* c, uint32_t a0, uint32_t a1,
                                     uint32_t a2, uint32_t a3,
                                     uint32_t b0, uint32_t b1) {
    asm volatile(
        "mma.sync.aligned.m16n8k8.row.col.f32.tf32.tf32.f32 "
        "{%0,%1,%2,%3}, {%4,%5,%6,%7}, {%8,%9}, {%0,%1,%2,%3};"
        : "+f"(c[0]), "+f"(c[1]), "+f"(c[2]), "+f"(c[3])
        : "r"(a0), "r"(a1), "r"(a2), "r"(a3), "r"(b0), "r"(b1));
}

__device__ __forceinline__ void cp16(uint32_t dst, const float* src) {
    asm volatile("cp.async.cg.shared.global [%0], [%1], 16;"
                 :: "r"(dst), "l"(src) : "memory");
}

// W chunk c -> smem buffer c%3 (scratch already rounded + permuted)
__device__ __forceinline__ void issue_w(int c, uint32_t sb, int tid) {
    const int tower = c >> 4, ch = c & 15, buf = c % 3;
    const float* src0 = wscr + tower * (LOUT * KF) + ch * KC;
    const uint32_t dst0 = sb + S_W + buf * W_BYTES;
#pragma unroll
    for (int i = 0; i < 4; i++) {            // 2048 16B segments / 512 thr
        int seg = tid + i * NTHREADS;
        int row = seg >> 3, q = seg & 7;
        cp16(dst0 + row * (WST * 4) + q * 16, src0 + row * KF + q * 4);
    }
    asm volatile("cp.async.commit_group;" ::: "memory");
}

__device__ __forceinline__ void ldg_a(float4* pref, const float* lut,
                                      const int* idx, int kc, int tid) {
#pragma unroll
    for (int i = 0; i < 2; i++) {            // 1024 16B segments / 512 thr
        int seg = tid + i * NTHREADS;
        int row = seg >> 3, q = seg & 7;
        pref[i] = __ldg(reinterpret_cast<const float4*>(
            lut + (size_t)idx[row] * KF + kc + q * 4));
    }
}

// store A chunk with rna rounding + permutation: k=4j+t -> pos t*8+j
__device__ __forceinline__ void sts_a(const float4* pref, char* smem, int c,
                                      int tid) {
    float* base = (float*)(smem + S_A + (c & 1) * A_BYTES);
#pragma unroll
    for (int i = 0; i < 2; i++) {
        int seg = tid + i * NTHREADS;
        int row = seg >> 3, q = seg & 7;
        float* rp = base + row * AST + q;
        rp[0]  = tf32f(pref[i].x);
        rp[8]  = tf32f(pref[i].y);
        rp[16] = tf32f(pref[i].z);
        rp[24] = tf32f(pref[i].w);
    }
}

// --------------------------- prep kernel ------------------------------------

__global__ void prep_kernel(const float* __restrict__ uW,
                            const float* __restrict__ iW) {
    int o = blockIdx.x * 256 + threadIdx.x;        // [0, 262144)
    int tower = o >> 17;
    int l = (o >> 9) & (LOUT - 1);
    int p = o & (KF - 1);
    int ch = p >> 5, t = (p >> 3) & 3, j = p & 7;
    const float* W = tower ? iW : uW;
    wscr[o] = tf32f(W[l * KF + ch * KC + 4 * j + t]);
}

// --------------------------- main kernel ------------------------------------

__global__ void __launch_bounds__(NTHREADS, 1) towers_kernel(
    const int* __restrict__ x,
    const float* __restrict__ ulut, const float* __restrict__ ilut,
    const float* __restrict__ ubias, const float* __restrict__ ibias,
    float* __restrict__ out) {
    extern __shared__ char smem[];
    uint32_t sb;
    asm("{ .reg .u64 t; cvta.to.shared.u64 t, %1; cvt.u32.u64 %0, t; }"
        : "=r"(sb) : "l"(smem));
    const int tid  = threadIdx.x;
    const int lane = tid & 31;
    const int wid  = tid >> 5;
    const int wm   = wid & 3;        // 4 row groups of 32 rows
    const int wn   = wid >> 2;       // 4 col groups of 64 latents
    const int g    = lane >> 2;
    const int t    = lane & 3;

    int*   idxu = (int*)(smem + S_IDXU);
    int*   idxi = (int*)(smem + S_IDXI);
    float* ubS  = (float*)(smem + S_UB);
    float* ibS  = (float*)(smem + S_IB);
    float* part = (float*)(smem + S_PART);
    __nv_bfloat16* ulat = (__nv_bfloat16*)(smem + S_ULAT);

    if (tid < LOUT) {
        ubS[tid] = ubias[tid];
        ibS[tid] = ibias[tid];
    }
    if (tid < TB) {
        part[tid] = 0.f;
        int gg = blockIdx.x * TB + tid;
        idxu[tid] = x[2 * gg];
        idxi[tid] = x[2 * gg + 1];
    }
    __syncthreads();

    issue_w(0, sb, tid);
    issue_w(1, sb, tid);

    float4 pref[2];
    ldg_a(pref, ulut, idxu, 0, tid);

    float acc[2][8][4];
#pragma unroll
    for (int mt = 0; mt < 2; mt++)
#pragma unroll
        for (int nt = 0; nt < 8; nt++)
#pragma unroll
            for (int i = 0; i < 4; i++) acc[mt][nt][i] = 0.f;

    for (int c = 0; c < NCHUNK; c++) {
        // 1. store prefetched A (rounds + permutes); buffer (c&1) free:
        //    last reader MMA(c-2) is CTA-wide complete past sync(c-1).
        sts_a(pref, smem, c, tid);

        // 2. prefetch next A chunk
        if (c + 1 < NCHUNK) {
            int c2 = c + 1;
            bool t2 = (c2 >= NCHUNK / 2);
            ldg_a(pref, t2 ? ilut : ulut, t2 ? idxi : idxu,
                  (c2 & 15) * KC, tid);
        }

        // 3. ensure W chunk c landed (newest outstanding group is c+1)
        if (c <= NCHUNK - 3)
            asm volatile("cp.async.wait_group 1;" ::: "memory");
        else
            asm volatile("cp.async.wait_group 0;" ::: "memory");
        __syncthreads();

        // 4. refill W pipeline (post-sync: buffer (c+2)%3 readers done)
        if (c + 2 < NCHUNK) issue_w(c + 2, sb, tid);

        // 5. MMA on chunk c
        const float* A  = (const float*)(smem + S_A + (c & 1) * A_BYTES);
        const float* Bs = (const float*)(smem + S_W + (c % 3) * W_BYTES);
#pragma unroll
        for (int h = 0; h < 2; h++) {        // two k-step pairs
            float4 alo[2], ahi[2];
#pragma unroll
            for (int mt = 0; mt < 2; mt++) {
                const int r0 = wm * 32 + mt * 16 + g;
                alo[mt] = *(const float4*)(A + r0 * AST + t * 8 + h * 4);
                ahi[mt] = *(const float4*)(A + (r0 + 8) * AST + t * 8 + h * 4);
            }
#pragma unroll
            for (int ntb = 0; ntb < 2; ntb++) {   // 4 nt at a time
                float4 bv[4];
#pragma unroll
                for (int n4 = 0; n4 < 4; n4++) {
                    const int n0 = wn * 64 + (ntb * 4 + n4) * 8 + g;
                    bv[n4] = *(const float4*)(Bs + n0 * WST + t * 8 + h * 4);
                }
#pragma unroll
                for (int sp = 0; sp < 2; sp++) {
#pragma unroll
                    for (int mt = 0; mt < 2; mt++) {
                        const float* al = (const float*)&alo[mt];
                        const float* ah = (const float*)&ahi[mt];
                        uint32_t a0 = __float_as_uint(al[2 * sp]);
                        uint32_t a1 = __float_as_uint(ah[2 * sp]);
                        uint32_t a2 = __float_as_uint(al[2 * sp + 1]);
                        uint32_t a3 = __float_as_uint(ah[2 * sp + 1]);
#pragma unroll
                        for (int n4 = 0; n4 < 4; n4++) {
                            const float* bp = (const float*)&bv[n4];
                            mma8(acc[mt][ntb * 4 + n4],
                                 a0, a1, a2, a3,
                                 __float_as_uint(bp[2 * sp]),
                                 __float_as_uint(bp[2 * sp + 1]));
                        }
                    }
                }
            }
        }

        // 6. user-tower epilogue: bias + relu -> bf16 smem, reset acc
        if (c == NCHUNK / 2 - 1) {
#pragma unroll
            for (int mt = 0; mt < 2; mt++) {
                const int r0 = wm * 32 + mt * 16 + g;
#pragma unroll
                for (int nt = 0; nt < 8; nt++) {
                    const int c0 = wn * 64 + nt * 8 + 2 * t;
                    float u0 = fmaxf(acc[mt][nt][0] + ubS[c0],     0.f);
                    float u1 = fmaxf(acc[mt][nt][1] + ubS[c0 + 1], 0.f);
                    float u2 = fmaxf(acc[mt][nt][2] + ubS[c0],     0.f);
                    float u3 = fmaxf(acc[mt][nt][3] + ubS[c0 + 1], 0.f);
                    *(__nv_bfloat162*)(ulat + r0 * ULST + c0) =
                        __floats2bfloat162_rn(u0, u1);
                    *(__nv_bfloat162*)(ulat + (r0 + 8) * ULST + c0) =
                        __floats2bfloat162_rn(u2, u3);
                    acc[mt][nt][0] = acc[mt][nt][1] = 0.f;
                    acc[mt][nt][2] = acc[mt][nt][3] = 0.f;
                }
            }
        }
    }

    // item-tower epilogue: bias+relu, product with user latent, row-reduce
#pragma unroll
    for (int mt = 0; mt < 2; mt++) {
        const int r0 = wm * 32 + mt * 16 + g;
        float s0 = 0.f, s1 = 0.f;
#pragma unroll
        for (int nt = 0; nt < 8; nt++) {
            const int c0 = wn * 64 + nt * 8 + 2 * t;
            float v0 = fmaxf(acc[mt][nt][0] + ibS[c0],     0.f);
            float v1 = fmaxf(acc[mt][nt][1] + ibS[c0 + 1], 0.f);
            float v2 = fmaxf(acc[mt][nt][2] + ibS[c0],     0.f);
            float v3 = fmaxf(acc[mt][nt][3] + ibS[c0 + 1], 0.f);
            float2 u01 = __bfloat1622float2(
                *(__nv_bfloat162*)(ulat + r0 * ULST + c0));
            float2 u23 = __bfloat1622float2(
                *(__nv_bfloat162*)(ulat + (r0 + 8) * ULST + c0));
            s0 = fmaf(u01.x, v0, fmaf(u01.y, v1, s0));
            s1 = fmaf(u23.x, v2, fmaf(u23.y, v3, s1));
        }
        s0 += __shfl_xor_sync(0xffffffffu, s0, 1);
        s0 += __shfl_xor_sync(0xffffffffu, s0, 2);
        s1 += __shfl_xor_sync(0xffffffffu, s1, 1);
        s1 += __shfl_xor_sync(0xffffffffu, s1, 2);
        if (t == 0) {
            atomicAdd(&part[r0], s0);
            atomicAdd(&part[r0 + 8], s1);
        }
    }
    __syncthreads();

    if (tid < TB) out[blockIdx.x * TB + tid] = part[tid];
}

// --------------------------- launch -----------------------------------------

extern "C" void kernel_launch(void* const* d_in, const int* in_sizes, int n_in,
                              void* d_out, int out_size) {
    const int* x      = (const int*)d_in[0];
    const float* ulut = (const float*)d_in[1];
    const float* ilut = (const float*)d_in[2];
    const float* uW   = (const float*)d_in[3];
    const float* ub   = (const float*)d_in[4];
    const float* iW   = (const float*)d_in[5];
    const float* ib   = (const float*)d_in[6];
    float* out        = (float*)d_out;

    prep_kernel<<<2 * LOUT * KF / 256, 256>>>(uW, iW);

    cudaFuncSetAttribute(towers_kernel,
                         cudaFuncAttributeMaxDynamicSharedMemorySize, S_TOTAL);
    int grid = out_size / TB;   // 128
    towers_kernel<<<grid, NTHREADS, S_TOTAL>>>(x, ulut, ilut, ub, ib, out);
}